// round 7
// baseline (speedup 1.0000x reference)
#include <cuda_runtime.h>

// RoiPooling: crop_and_resize(img[0], 2048 boxes, crop=7) over 512 channels.
// Occupancy-first layout: one CTA = one (box, output_row); grid (2048, 7),
// 128 threads = 512 channels as float4. 12 independent upfront LDG.128
// (two image rows x 6 unique columns), compile-time BASE_X selects, 7
// streaming STG.128. No caches, no register pressure, max MLP.

#define IMG_H 28
#define IMG_W 28
#define C4    128          // 512 channels / 4
#define POOLN 7
#define NBOX  2048
#define ROWSTRIDE (IMG_W * C4)   // float4 elems per image row

__global__ __launch_bounds__(128, 5) void roi_pool_kernel(
    const float4* __restrict__ img4,   // img[0] as float4: (28*28, 128)
    const float*  __restrict__ rois,
    float4* __restrict__ out4)
{
    // floor(j * 27*4/(28*6)) for j=0..6; j*sx stays >=0.07 from any integer,
    // far beyond f32 rounding wiggle, so ax[j]-ax[0] ∈ {BASE, BASE+1}.
    const int BASE_X[POOLN] = {0, 0, 1, 1, 2, 3, 3};

    const int box = blockIdx.x;
    const int i   = blockIdx.y;            // output row 0..6
    const int tid = threadIdx.x;           // channel-quad 0..127

    const float x1 = rois[box * 5 + 3];
    const float y1 = rois[box * 5 + 4];
    const float win = (float)(4.0 / 28.0);
    // Match JAX numerics: ((x1+win)-x1)*27/6 in f32
    const float sx = (((x1 + win) - x1) * 27.0f) / 6.0f;
    const float sy = (((y1 + win) - y1) * 27.0f) / 6.0f;
    const float fx = x1 * 27.0f;
    const float fy = y1 * 27.0f;

    // ---- y for this CTA's output row ----
    const float ys = fy + (float)i * sy;
    const float yf = floorf(ys);
    const float ly = ys - yf;
    const int ya = (int)yf;                // rois >= 0 so ys >= 0
    const int t = min(ya, IMG_H - 1);
    const int b = min(ya + 1, IMG_H - 1);
    const float my = (ys <= 27.0f) ? 1.0f : 0.0f;
    const float wA = (1.0f - ly) * my;
    const float wB = ly * my;

    // ---- x weights / selects (uniform per CTA) ----
    const int x_lo = (int)floorf(fx);
    float w0[POOLN], w1[POOLN];
    unsigned condm = 0;
#pragma unroll
    for (int j = 0; j < POOLN; j++) {
        float xs = fx + (float)j * sx;
        float xf = floorf(xs);
        float l = xs - xf;
        int ax = (int)xf;
        if ((ax - x_lo) > BASE_X[j]) condm |= (1u << j);
        float m = (xs <= 27.0f) ? 1.0f : 0.0f;
        w0[j] = m * (1.0f - l);
        w1[j] = m * l;
    }

    int colofs[6];
#pragma unroll
    for (int k = 0; k < 6; k++)
        colofs[k] = min(x_lo + k, IMG_W - 1) * C4;

    // ---- 12 independent loads, all issued before any use ----
    const float4* base_img = img4 + tid;
    const float4* rpT = base_img + t * ROWSTRIDE;
    const float4* rpB = base_img + b * ROWSTRIDE;
    float4 pT[6], pB[6];
#pragma unroll
    for (int k = 0; k < 6; k++) {
        pT[k] = __ldg(rpT + colofs[k]);
        pB[k] = __ldg(rpB + colofs[k]);
    }

    float4* outp = out4 + ((size_t)box * (POOLN * POOLN) + i * POOLN) * C4 + tid;

#pragma unroll
    for (int j = 0; j < POOLN; j++) {
        const int bx = BASE_X[j];
        float4 t0, t1, b0, b1;
        if ((condm >> j) & 1) {
            t0 = pT[bx + 1]; t1 = pT[bx + 2];
            b0 = pB[bx + 1]; b1 = pB[bx + 2];
        } else {
            t0 = pT[bx];     t1 = pT[bx + 1];
            b0 = pB[bx];     b1 = pB[bx + 1];
        }
        float a0 = w0[j], a1 = w1[j];
        float4 v;
        v.x = (t0.x * a0 + t1.x * a1) * wA + (b0.x * a0 + b1.x * a1) * wB;
        v.y = (t0.y * a0 + t1.y * a1) * wA + (b0.y * a0 + b1.y * a1) * wB;
        v.z = (t0.z * a0 + t1.z * a1) * wA + (b0.z * a0 + b1.z * a1) * wB;
        v.w = (t0.w * a0 + t1.w * a1) * wA + (b0.w * a0 + b1.w * a1) * wB;
        __stcs(outp + j * C4, v);
    }
}

extern "C" void kernel_launch(void* const* d_in, const int* in_sizes, int n_in,
                              void* d_out, int out_size) {
    const float* img  = (const float*)d_in[0];
    const float* rois = (const float*)d_in[1];
    float* out = (float*)d_out;
    (void)in_sizes; (void)n_in; (void)out_size;
    dim3 grid(NBOX, POOLN);
    roi_pool_kernel<<<grid, 128>>>((const float4*)img, rois, (float4*)out);
}

// round 9
// speedup vs baseline: 1.1179x; 1.1179x over previous
#include <cuda_runtime.h>

// RoiPooling: crop_and_resize(img[0], 2048 boxes, crop=7) over 512 channels.
// CTA = box, 128 threads = 512 channels as float4. Per output row: 12
// independent LDG.128 (two image rows x 6 unique patch columns), y-blend into
// ry[6], then each of the 7 outputs is a select-free 3-tap FMA using per-box
// precomputed window weights Wa/Wb/Wc (the corner choice is folded into which
// taps are zero). Setup runs once per box. No register caches, no spills.

#define IMG_H 28
#define IMG_W 28
#define C4    128          // 512 channels / 4
#define POOLN 7
#define NBOX  2048
#define ROWSTRIDE (IMG_W * C4)   // float4 elems per image row

__global__ __launch_bounds__(128, 4) void roi_pool_kernel(
    const float4* __restrict__ img4,   // img[0] as float4: (28*28, 128)
    const float*  __restrict__ rois,
    float4* __restrict__ out4)
{
    // floor(j * 27*4/(28*6)) for j=0..6; j*sx stays >=0.07 from any integer,
    // far beyond f32 rounding wiggle, so ax[j]-ax[0] ∈ {BASE, BASE+1}.
    const int BASE_X[POOLN] = {0, 0, 1, 1, 2, 3, 3};

    const int box = blockIdx.x;
    const int tid = threadIdx.x;           // channel-quad 0..127

    const float x1 = rois[box * 5 + 3];
    const float y1 = rois[box * 5 + 4];
    const float win = (float)(4.0 / 28.0);
    // Match JAX numerics: ((x1+win)-x1)*27/6 in f32
    const float sx = (((x1 + win) - x1) * 27.0f) / 6.0f;
    const float sy = (((y1 + win) - y1) * 27.0f) / 6.0f;
    const float fx = x1 * 27.0f;
    const float fy = y1 * 27.0f;

    // ---- per-box x setup: 3-tap window weights, select-free hot loop ----
    const int x_lo = (int)floorf(fx);      // rois >= 0 so fx >= 0
    float Wa[POOLN], Wb[POOLN], Wc[POOLN];
#pragma unroll
    for (int j = 0; j < POOLN; j++) {
        float xs = fx + (float)j * sx;
        float xf = floorf(xs);
        float l = xs - xf;
        int ax = (int)xf;
        bool c = (ax - x_lo) > BASE_X[j];  // sample sits one column right
        float m = (xs <= 27.0f) ? 1.0f : 0.0f;
        float u0 = m * (1.0f - l);
        float u1 = m * l;
        Wa[j] = c ? 0.0f : u0;
        Wb[j] = c ? u0   : u1;
        Wc[j] = c ? u1   : 0.0f;
    }

    int colofs[6];
#pragma unroll
    for (int k = 0; k < 6; k++)
        colofs[k] = min(x_lo + k, IMG_W - 1) * C4;

    const float4* base_img = img4 + tid;
    float4* outp = out4 + (size_t)box * (POOLN * POOLN) * C4 + tid;

#pragma unroll
    for (int i = 0; i < POOLN; i++) {
        float ys = fy + (float)i * sy;
        float yf = floorf(ys);
        float ly = ys - yf;
        int ya = (int)yf;
        int t = min(ya, IMG_H - 1);
        int b = min(ya + 1, IMG_H - 1);
        float my = (ys <= 27.0f) ? 1.0f : 0.0f;
        float wA = (1.0f - ly) * my;
        float wB = ly * my;

        // 12 independent loads for this output row
        const float4* rpT = base_img + t * ROWSTRIDE;
        const float4* rpB = base_img + b * ROWSTRIDE;
        float4 pT[6], pB[6];
#pragma unroll
        for (int k = 0; k < 6; k++) {
            pT[k] = __ldg(rpT + colofs[k]);
            pB[k] = __ldg(rpB + colofs[k]);
        }

        // y-blend the patch row
        float4 ry[6];
#pragma unroll
        for (int k = 0; k < 6; k++) {
            ry[k].x = pT[k].x * wA + pB[k].x * wB;
            ry[k].y = pT[k].y * wA + pB[k].y * wB;
            ry[k].z = pT[k].z * wA + pB[k].z * wB;
            ry[k].w = pT[k].w * wA + pB[k].w * wB;
        }

        // 7 select-free 3-tap outputs
#pragma unroll
        for (int j = 0; j < POOLN; j++) {
            const int bx = BASE_X[j];
            float a = Wa[j], bb = Wb[j], cc = Wc[j];
            float4 v;
            v.x = ry[bx].x * a + ry[bx + 1].x * bb + ry[bx + 2].x * cc;
            v.y = ry[bx].y * a + ry[bx + 1].y * bb + ry[bx + 2].y * cc;
            v.z = ry[bx].z * a + ry[bx + 1].z * bb + ry[bx + 2].z * cc;
            v.w = ry[bx].w * a + ry[bx + 1].w * bb + ry[bx + 2].w * cc;
            __stcs(outp + (i * POOLN + j) * C4, v);
        }
    }
}

extern "C" void kernel_launch(void* const* d_in, const int* in_sizes, int n_in,
                              void* d_out, int out_size) {
    const float* img  = (const float*)d_in[0];
    const float* rois = (const float*)d_in[1];
    float* out = (float*)d_out;
    (void)in_sizes; (void)n_in; (void)out_size;
    roi_pool_kernel<<<NBOX, 128>>>((const float4*)img, rois, (float4*)out);
}

// round 10
// speedup vs baseline: 1.1594x; 1.0371x over previous
#include <cuda_runtime.h>

// RoiPooling: crop_and_resize(img[0], 2048 boxes, crop=7) over 512 channels.
// CTA = box, 128 threads = 512 channels as float4.
// Raw 2-row patch register cache (pT/pB, 6 float4 each): image rows are
// nondecreasing with step <= 1 across output rows, so each advance is
// pT <- pB + ONE fresh 6-load row (~36 LDG.128/box vs 84 uncached).
// Outputs use R8's select-free 3-tap window weights (corner choice folded
// into zero taps). All branches CTA-uniform.

#define IMG_H 28
#define IMG_W 28
#define C4    128          // 512 channels / 4
#define POOLN 7
#define NBOX  2048
#define ROWSTRIDE (IMG_W * C4)   // float4 elems per image row

#define LOADROW(rowc, dst) do {                                               \
    const float4* rp_ = base_img + (rowc) * ROWSTRIDE;                        \
    _Pragma("unroll")                                                         \
    for (int k_ = 0; k_ < 6; k_++) (dst)[k_] = __ldg(rp_ + colofs[k_]);       \
} while (0)

__global__ __launch_bounds__(128, 4) void roi_pool_kernel(
    const float4* __restrict__ img4,   // img[0] as float4: (28*28, 128)
    const float*  __restrict__ rois,
    float4* __restrict__ out4)
{
    // floor(j * 27*4/(28*6)) for j=0..6; j*sx stays >=0.07 from any integer,
    // far beyond f32 rounding wiggle, so ax[j]-ax[0] ∈ {BASE, BASE+1}.
    const int BASE_X[POOLN] = {0, 0, 1, 1, 2, 3, 3};

    const int box = blockIdx.x;
    const int tid = threadIdx.x;           // channel-quad 0..127

    const float x1 = rois[box * 5 + 3];
    const float y1 = rois[box * 5 + 4];
    const float win = (float)(4.0 / 28.0);
    // Match JAX numerics: ((x1+win)-x1)*27/6 in f32
    const float sx = (((x1 + win) - x1) * 27.0f) / 6.0f;
    const float sy = (((y1 + win) - y1) * 27.0f) / 6.0f;
    const float fx = x1 * 27.0f;
    const float fy = y1 * 27.0f;

    // ---- per-box x setup: select-free 3-tap window weights ----
    const int x_lo = (int)floorf(fx);      // rois >= 0 so fx >= 0
    float Wa[POOLN], Wb[POOLN], Wc[POOLN];
#pragma unroll
    for (int j = 0; j < POOLN; j++) {
        float xs = fx + (float)j * sx;
        float xf = floorf(xs);
        float l = xs - xf;
        int ax = (int)xf;
        bool c = (ax - x_lo) > BASE_X[j];  // sample sits one column right
        float m = (xs <= 27.0f) ? 1.0f : 0.0f;
        float u0 = m * (1.0f - l);
        float u1 = m * l;
        Wa[j] = c ? 0.0f : u0;
        Wb[j] = c ? u0   : u1;
        Wc[j] = c ? u1   : 0.0f;
    }

    int colofs[6];
#pragma unroll
    for (int k = 0; k < 6; k++)
        colofs[k] = min(x_lo + k, IMG_W - 1) * C4;

    const float4* base_img = img4 + tid;
    float4* outp = out4 + (size_t)box * (POOLN * POOLN) * C4 + tid;

    // ---- raw 2-row patch cache ----
    float4 pT[6], pB[6];
    int ct, cb;
    {
        // i = 0 init
        float ys0 = fy;
        int ya0 = (int)floorf(ys0);
        ct = min(ya0, IMG_H - 1);
        cb = min(ya0 + 1, IMG_H - 1);
        LOADROW(ct, pT);
        if (cb != ct) {
            LOADROW(cb, pB);
        } else {
#pragma unroll
            for (int k = 0; k < 6; k++) pB[k] = pT[k];
        }
    }

#pragma unroll
    for (int i = 0; i < POOLN; i++) {
        float ys = fy + (float)i * sy;
        float yf = floorf(ys);
        float ly = ys - yf;
        int ya = (int)yf;
        int t = min(ya, IMG_H - 1);
        int b = min(ya + 1, IMG_H - 1);
        float my = (ys <= 27.0f) ? 1.0f : 0.0f;
        float wA = (1.0f - ly) * my;
        float wB = ly * my;

        if (i > 0 && t != ct) {
            // advance by exactly one image row: new top == old bottom
#pragma unroll
            for (int k = 0; k < 6; k++) pT[k] = pB[k];
            if (b != t) {
                LOADROW(b, pB);
            } else {
#pragma unroll
                for (int k = 0; k < 6; k++) pB[k] = pT[k];
            }
            ct = t; cb = b;
        }

        // y-blend the patch row (transient)
        float4 ry[6];
#pragma unroll
        for (int k = 0; k < 6; k++) {
            ry[k].x = pT[k].x * wA + pB[k].x * wB;
            ry[k].y = pT[k].y * wA + pB[k].y * wB;
            ry[k].z = pT[k].z * wA + pB[k].z * wB;
            ry[k].w = pT[k].w * wA + pB[k].w * wB;
        }

        // 7 select-free 3-tap outputs
#pragma unroll
        for (int j = 0; j < POOLN; j++) {
            const int bx = BASE_X[j];
            float a = Wa[j], bb = Wb[j], cc = Wc[j];
            float4 v;
            v.x = ry[bx].x * a + ry[bx + 1].x * bb + ry[bx + 2].x * cc;
            v.y = ry[bx].y * a + ry[bx + 1].y * bb + ry[bx + 2].y * cc;
            v.z = ry[bx].z * a + ry[bx + 1].z * bb + ry[bx + 2].z * cc;
            v.w = ry[bx].w * a + ry[bx + 1].w * bb + ry[bx + 2].w * cc;
            __stcs(outp + (i * POOLN + j) * C4, v);
        }
    }
}

extern "C" void kernel_launch(void* const* d_in, const int* in_sizes, int n_in,
                              void* d_out, int out_size) {
    const float* img  = (const float*)d_in[0];
    const float* rois = (const float*)d_in[1];
    float* out = (float*)d_out;
    (void)in_sizes; (void)n_in; (void)out_size;
    roi_pool_kernel<<<NBOX, 128>>>((const float4*)img, rois, (float4*)out);
}